// round 1
// baseline (speedup 1.0000x reference)
#include <cuda_runtime.h>
#include <cstdint>

#define HEADS 16
#define HD    32
#define CDIM  512
#define NTOK  64
#define BWIN  2048
#define NWIN  256

// ---------------- scratch (static device memory, no allocs) ----------------
__device__ float g_qkv[(size_t)BWIN * NTOK * 3 * CDIM];   // [B*N, 1536]  (q|k|v)
__device__ float g_att[(size_t)BWIN * NTOK * CDIM];       // [B*N, 512]   pre-proj
__device__ float g_rpb[HEADS * NTOK * NTOK];              // expanded rel-pos bias [h][n][m]
__device__ float g_qkvb[3 * CDIM];                        // [q_bias | 0 | v_bias]

// ---------------- helpers ----------------
__device__ __forceinline__ float f2tf(float x) {
    uint32_t u;
    asm("cvt.rna.tf32.f32 %0, %1;" : "=r"(u) : "f"(x));
    return __uint_as_float(u);
}

__device__ __forceinline__ void mma_tf32(float c[4],
        uint32_t a0, uint32_t a1, uint32_t a2, uint32_t a3,
        uint32_t b0, uint32_t b1) {
    asm volatile(
        "mma.sync.aligned.m16n8k8.row.col.f32.tf32.tf32.f32 "
        "{%0,%1,%2,%3}, {%4,%5,%6,%7}, {%8,%9}, {%0,%1,%2,%3};"
        : "+f"(c[0]), "+f"(c[1]), "+f"(c[2]), "+f"(c[3])
        : "r"(a0), "r"(a1), "r"(a2), "r"(a3), "r"(b0), "r"(b1));
}

// ---------------- prep: expand rpb gather + build qkv bias ----------------
__global__ void prep_kernel(const float* __restrict__ q_bias,
                            const float* __restrict__ v_bias,
                            const float* __restrict__ rpb_table,
                            const int*   __restrict__ rel_index) {
    int idx = blockIdx.x * 256 + threadIdx.x;
    if (idx < 3 * CDIM) {
        float v = 0.f;
        if (idx < CDIM)           v = q_bias[idx];
        else if (idx >= 2 * CDIM) v = v_bias[idx - 2 * CDIM];
        g_qkvb[idx] = v;
    }
    if (idx < HEADS * NTOK * NTOK) {
        int h  = idx >> 12;      // / 4096
        int nm = idx & 4095;
        g_rpb[idx] = rpb_table[rel_index[nm] * HEADS + h];
    }
}

// ---------------- tf32 GEMM: C[M,N] = A[M,K] * B[N,K]^T + bias[N] ----------------
// BM=128, BN=128, BK=32; 8 warps in 4(M) x 2(N); warp tile 32x64.
__global__ __launch_bounds__(256, 2)
void gemm_tf32(const float* __restrict__ A, const float* __restrict__ B,
               const float* __restrict__ bias, float* __restrict__ Cout,
               int N, int K) {
    __shared__ float As[128][36];
    __shared__ float Bs[128][36];

    const int tid  = threadIdx.x;
    const int lane = tid & 31;
    const int warp = tid >> 5;
    const int wm = warp >> 1;        // 0..3
    const int wn = warp & 1;         // 0..1
    const int m0 = blockIdx.y * 128;
    const int n0 = blockIdx.x * 128;

    float c[2][8][4];
#pragma unroll
    for (int mi = 0; mi < 2; mi++)
#pragma unroll
        for (int ni = 0; ni < 8; ni++)
#pragma unroll
            for (int r = 0; r < 4; r++) c[mi][ni][r] = 0.f;

    const float* Ap = A + (size_t)m0 * K;
    const float* Bp = B + (size_t)n0 * K;

    for (int kb = 0; kb < K; kb += 32) {
#pragma unroll
        for (int i = 0; i < 4; i++) {
            int f   = tid + 256 * i;         // 0..1023
            int row = f >> 3;
            int c4  = (f & 7) * 4;
            float4 va = *(const float4*)(Ap + (size_t)row * K + kb + c4);
            float4 vb = *(const float4*)(Bp + (size_t)row * K + kb + c4);
            va.x = f2tf(va.x); va.y = f2tf(va.y); va.z = f2tf(va.z); va.w = f2tf(va.w);
            vb.x = f2tf(vb.x); vb.y = f2tf(vb.y); vb.z = f2tf(vb.z); vb.w = f2tf(vb.w);
            *(float4*)&As[row][c4] = va;
            *(float4*)&Bs[row][c4] = vb;
        }
        __syncthreads();
#pragma unroll
        for (int ks = 0; ks < 4; ks++) {
            int kc = ks * 8 + (lane & 3);
            uint32_t a[2][4];
#pragma unroll
            for (int mi = 0; mi < 2; mi++) {
                int r = wm * 32 + mi * 16 + (lane >> 2);
                a[mi][0] = __float_as_uint(As[r][kc]);
                a[mi][1] = __float_as_uint(As[r + 8][kc]);
                a[mi][2] = __float_as_uint(As[r][kc + 4]);
                a[mi][3] = __float_as_uint(As[r + 8][kc + 4]);
            }
#pragma unroll
            for (int ni = 0; ni < 8; ni++) {
                int n = wn * 64 + ni * 8 + (lane >> 2);
                uint32_t b0 = __float_as_uint(Bs[n][kc]);
                uint32_t b1 = __float_as_uint(Bs[n][kc + 4]);
                mma_tf32(c[0][ni], a[0][0], a[0][1], a[0][2], a[0][3], b0, b1);
                mma_tf32(c[1][ni], a[1][0], a[1][1], a[1][2], a[1][3], b0, b1);
            }
        }
        __syncthreads();
    }

    // epilogue
#pragma unroll
    for (int mi = 0; mi < 2; mi++) {
        int r = m0 + wm * 32 + mi * 16 + (lane >> 2);
#pragma unroll
        for (int ni = 0; ni < 8; ni++) {
            int col = n0 + wn * 64 + ni * 8 + (lane & 3) * 2;
            float b0 = bias[col], b1 = bias[col + 1];
            *(float2*)(Cout + (size_t)r * N + col) =
                make_float2(c[mi][ni][0] + b0, c[mi][ni][1] + b1);
            *(float2*)(Cout + (size_t)(r + 8) * N + col) =
                make_float2(c[mi][ni][2] + b0, c[mi][ni][3] + b1);
        }
    }
}

// ---------------- fused window attention: one CTA per (window b, head h) ----------------
// 128 threads (4 warps). Each warp owns 16 query rows.
__global__ __launch_bounds__(128)
void attn_kernel(const float* __restrict__ mask) {
    __shared__ float q_s[64][36];
    __shared__ float k_s[64][36];
    __shared__ float v_s[64][40];
    __shared__ float s_s[64][68];
    __shared__ float rsum[64];

    const int tid  = threadIdx.x;
    const int lane = tid & 31;
    const int warp = tid >> 5;
    const int h = blockIdx.x;
    const int b = blockIdx.y;
    const int w = b & (NWIN - 1);

    const float* base = g_qkv + (size_t)b * NTOK * 3 * CDIM + h * HD;

    // load q,k,v tiles (64x32 each), convert to tf32
#pragma unroll
    for (int i = 0; i < 4; i++) {
        int f   = tid + 128 * i;      // 0..511
        int row = f >> 3;
        int c4  = (f & 7) * 4;
        const float* rp = base + (size_t)row * (3 * CDIM);
        float4 q = *(const float4*)(rp + c4);
        float4 k = *(const float4*)(rp + CDIM + c4);
        float4 v = *(const float4*)(rp + 2 * CDIM + c4);
        q.x = f2tf(q.x); q.y = f2tf(q.y); q.z = f2tf(q.z); q.w = f2tf(q.w);
        k.x = f2tf(k.x); k.y = f2tf(k.y); k.z = f2tf(k.z); k.w = f2tf(k.w);
        v.x = f2tf(v.x); v.y = f2tf(v.y); v.z = f2tf(v.z); v.w = f2tf(v.w);
        *(float4*)&q_s[row][c4] = q;
        *(float4*)&k_s[row][c4] = k;
        *(float4*)&v_s[row][c4] = v;
    }
    __syncthreads();

    // S = Q K^T  (warp w: rows 16w..16w+15; 8 ntiles of 8 key cols; 4 ksteps)
    float sc[8][4];
#pragma unroll
    for (int ni = 0; ni < 8; ni++)
#pragma unroll
        for (int r = 0; r < 4; r++) sc[ni][r] = 0.f;

#pragma unroll
    for (int ks = 0; ks < 4; ks++) {
        int kc = ks * 8 + (lane & 3);
        int r  = warp * 16 + (lane >> 2);
        uint32_t a0 = __float_as_uint(q_s[r][kc]);
        uint32_t a1 = __float_as_uint(q_s[r + 8][kc]);
        uint32_t a2 = __float_as_uint(q_s[r][kc + 4]);
        uint32_t a3 = __float_as_uint(q_s[r + 8][kc + 4]);
#pragma unroll
        for (int ni = 0; ni < 8; ni++) {
            int m = ni * 8 + (lane >> 2);
            mma_tf32(sc[ni], a0, a1, a2, a3,
                     __float_as_uint(k_s[m][kc]),
                     __float_as_uint(k_s[m][kc + 4]));
        }
    }

    const float scale = 0.17677669529663687f;   // 32^-0.5
    const float* rpbh = g_rpb + h * 4096;
    const float* mkw  = mask + (size_t)w * 4096;
#pragma unroll
    for (int ni = 0; ni < 8; ni++) {
        int r   = warp * 16 + (lane >> 2);
        int col = ni * 8 + (lane & 3) * 2;
        float2 rb0 = *(const float2*)(rpbh + r * 64 + col);
        float2 mk0 = *(const float2*)(mkw + r * 64 + col);
        s_s[r][col]     = sc[ni][0] * scale + rb0.x + mk0.x;
        s_s[r][col + 1] = sc[ni][1] * scale + rb0.y + mk0.y;
        float2 rb1 = *(const float2*)(rpbh + (r + 8) * 64 + col);
        float2 mk1 = *(const float2*)(mkw + (r + 8) * 64 + col);
        s_s[r + 8][col]     = sc[ni][2] * scale + rb1.x + mk1.x;
        s_s[r + 8][col + 1] = sc[ni][3] * scale + rb1.y + mk1.y;
    }
    __syncthreads();

    // softmax (unnormalized): 2 threads per row, store exp() as tf32, keep row sum
    {
        int row = tid >> 1;
        int c0  = (tid & 1) * 32;
        float mx = -1e30f;
#pragma unroll
        for (int j = 0; j < 32; j++) mx = fmaxf(mx, s_s[row][c0 + j]);
        mx = fmaxf(mx, __shfl_xor_sync(0xffffffff, mx, 1));
        float sum = 0.f;
#pragma unroll
        for (int j = 0; j < 32; j++) {
            float e = __expf(s_s[row][c0 + j] - mx);
            sum += e;
            s_s[row][c0 + j] = f2tf(e);
        }
        sum += __shfl_xor_sync(0xffffffff, sum, 1);
        if ((tid & 1) == 0) rsum[row] = sum;
    }
    __syncthreads();

    // O = P V   (k=64 -> 8 ksteps; 4 ntiles of 8 dims)
    float oc[4][4];
#pragma unroll
    for (int ni = 0; ni < 4; ni++)
#pragma unroll
        for (int r = 0; r < 4; r++) oc[ni][r] = 0.f;

#pragma unroll
    for (int ks = 0; ks < 8; ks++) {
        int kc = ks * 8 + (lane & 3);
        int r  = warp * 16 + (lane >> 2);
        uint32_t a0 = __float_as_uint(s_s[r][kc]);
        uint32_t a1 = __float_as_uint(s_s[r + 8][kc]);
        uint32_t a2 = __float_as_uint(s_s[r][kc + 4]);
        uint32_t a3 = __float_as_uint(s_s[r + 8][kc + 4]);
#pragma unroll
        for (int ni = 0; ni < 4; ni++) {
            int d = ni * 8 + (lane >> 2);
            mma_tf32(oc[ni], a0, a1, a2, a3,
                     __float_as_uint(v_s[kc][d]),
                     __float_as_uint(v_s[kc + 4][d]));
        }
    }

    float* outp = g_att + (size_t)b * NTOK * CDIM + h * HD;
#pragma unroll
    for (int ni = 0; ni < 4; ni++) {
        int r = warp * 16 + (lane >> 2);
        int d = ni * 8 + (lane & 3) * 2;
        float inv0 = 1.f / rsum[r];
        float inv1 = 1.f / rsum[r + 8];
        *(float2*)(outp + (size_t)r * CDIM + d) =
            make_float2(oc[ni][0] * inv0, oc[ni][1] * inv0);
        *(float2*)(outp + (size_t)(r + 8) * CDIM + d) =
            make_float2(oc[ni][2] * inv1, oc[ni][3] * inv1);
    }
}

// ---------------- launcher ----------------
extern "C" void kernel_launch(void* const* d_in, const int* in_sizes, int n_in,
                              void* d_out, int out_size) {
    const float* x         = (const float*)d_in[0];
    const float* mask      = (const float*)d_in[1];
    const float* qkv_w     = (const float*)d_in[2];
    const float* q_bias    = (const float*)d_in[3];
    const float* v_bias    = (const float*)d_in[4];
    const float* rpb_table = (const float*)d_in[5];
    const float* proj_w    = (const float*)d_in[6];
    const float* proj_b    = (const float*)d_in[7];
    const int*   rel_index = (const int*)d_in[8];
    float* out = (float*)d_out;

    void* p_qkv = nullptr; void* p_att = nullptr; void* p_qkvb = nullptr;
    cudaGetSymbolAddress(&p_qkv,  g_qkv);
    cudaGetSymbolAddress(&p_att,  g_att);
    cudaGetSymbolAddress(&p_qkvb, g_qkvb);

    // 1) expand rpb + build fused qkv bias
    prep_kernel<<<256, 256>>>(q_bias, v_bias, rpb_table, rel_index);

    // 2) QKV GEMM: [131072,512] x [1536,512]^T -> g_qkv
    gemm_tf32<<<dim3(1536 / 128, (BWIN * NTOK) / 128), 256>>>(
        x, qkv_w, (const float*)p_qkvb, (float*)p_qkv, 3 * CDIM, CDIM);

    // 3) fused window attention -> g_att
    attn_kernel<<<dim3(HEADS, BWIN), 128>>>(mask);

    // 4) proj GEMM: [131072,512] x [512,512]^T -> d_out
    gemm_tf32<<<dim3(CDIM / 128, (BWIN * NTOK) / 128), 256>>>(
        (const float*)p_att, proj_w, proj_b, out, CDIM, CDIM);
}

// round 4
// speedup vs baseline: 1.6833x; 1.6833x over previous
#include <cuda_runtime.h>
#include <cuda_fp16.h>
#include <cstdint>

#define HEADS 16
#define CDIM  512
#define NTOK  64
#define BWIN  2048
#define NWIN  256
#define MROWS (BWIN * NTOK)        // 131072

// ---------------- static scratch ----------------
__device__ __half g_x_h[(size_t)MROWS * CDIM];          // x in half
__device__ __half g_qkv_h[(size_t)MROWS * 3 * CDIM];    // qkv in half
__device__ __half g_att_h[(size_t)MROWS * CDIM];        // attn out in half
__device__ __half g_wqkv_h[3 * CDIM * CDIM];
__device__ __half g_wproj_h[CDIM * CDIM];
__device__ float  g_rpb[HEADS * NTOK * NTOK];
__device__ float  g_qkvb[3 * CDIM];

// ---------------- helpers ----------------
__device__ __forceinline__ uint32_t s2u(const void* p) {
    uint32_t a;
    asm("{ .reg .u64 t; cvta.to.shared.u64 t, %1; cvt.u32.u64 %0, t; }" : "=r"(a) : "l"(p));
    return a;
}
__device__ __forceinline__ void cpa16(uint32_t dst, const void* src) {
    asm volatile("cp.async.cg.shared.global [%0], [%1], 16;" :: "r"(dst), "l"(src) : "memory");
}
__device__ __forceinline__ void ldsm4(uint32_t r[4], uint32_t a) {
    asm volatile("ldmatrix.sync.aligned.m8n8.x4.shared.b16 {%0,%1,%2,%3}, [%4];"
                 : "=r"(r[0]), "=r"(r[1]), "=r"(r[2]), "=r"(r[3]) : "r"(a));
}
__device__ __forceinline__ void ldsm4t(uint32_t r[4], uint32_t a) {
    asm volatile("ldmatrix.sync.aligned.m8n8.x4.trans.shared.b16 {%0,%1,%2,%3}, [%4];"
                 : "=r"(r[0]), "=r"(r[1]), "=r"(r[2]), "=r"(r[3]) : "r"(a));
}
__device__ __forceinline__ void mma_f16(float c[4], const uint32_t a[4],
                                        uint32_t b0, uint32_t b1) {
    asm volatile(
        "mma.sync.aligned.m16n8k16.row.col.f32.f16.f16.f32 "
        "{%0,%1,%2,%3}, {%4,%5,%6,%7}, {%8,%9}, {%0,%1,%2,%3};"
        : "+f"(c[0]), "+f"(c[1]), "+f"(c[2]), "+f"(c[3])
        : "r"(a[0]), "r"(a[1]), "r"(a[2]), "r"(a[3]), "r"(b0), "r"(b1));
}

// ---------------- fp32 -> fp16 conversion ----------------
__global__ void cvt_kernel(const float* __restrict__ src, __half* __restrict__ dst, int n4) {
    int i = blockIdx.x * 256 + threadIdx.x;
    if (i < n4) {
        float4 v = ((const float4*)src)[i];
        ((half2*)dst)[2 * i]     = __floats2half2_rn(v.x, v.y);
        ((half2*)dst)[2 * i + 1] = __floats2half2_rn(v.z, v.w);
    }
}

// ---------------- prep: rpb gather + fused qkv bias ----------------
__global__ void prep_kernel(const float* __restrict__ q_bias,
                            const float* __restrict__ v_bias,
                            const float* __restrict__ rpb_table,
                            const int*   __restrict__ rel_index) {
    int idx = blockIdx.x * 256 + threadIdx.x;
    if (idx < 3 * CDIM) {
        float v = 0.f;
        if (idx < CDIM)           v = q_bias[idx];
        else if (idx >= 2 * CDIM) v = v_bias[idx - 2 * CDIM];
        g_qkvb[idx] = v;
    }
    if (idx < HEADS * NTOK * NTOK) {
        int h  = idx >> 12;
        int nm = idx & 4095;
        g_rpb[idx] = rpb_table[rel_index[nm] * HEADS + h];
    }
}

// ---------------- fp16 GEMM: C[M,N] = A[M,K] * B[N,K]^T + bias[N] ----------------
// CTA 128x128, BK=64, 4 warps (2x2) with 64x64 warp tiles, 3-stage cp.async.
#define BK      64
#define ROW_B   144                 // bytes per smem row (64 halves + 8 pad)
#define STG_A   (128 * ROW_B)       // 18432
#define STG     (2 * STG_A)         // 36864
#define NSTG    3
#define GEMM_SMEM (NSTG * STG)      // 110592

template<bool HOUT>
__global__ __launch_bounds__(128, 2)
void gemm_h(const __half* __restrict__ A, const __half* __restrict__ B,
            const float* __restrict__ bias, void* __restrict__ Cout,
            int N, int K) {
    extern __shared__ __align__(16) char smem[];
    const uint32_t sb = s2u(smem);
    const int tid = threadIdx.x, lane = tid & 31, warp = tid >> 5;
    const int wm = warp >> 1, wn = warp & 1;
    const int m0 = blockIdx.y * 128, n0 = blockIdx.x * 128;

    const __half* Ag = A + (size_t)m0 * K;
    const __half* Bg = B + (size_t)n0 * K;
    const int r8 = tid >> 3, c8 = tid & 7;

    float c[4][8][4];
#pragma unroll
    for (int mt = 0; mt < 4; mt++)
#pragma unroll
        for (int nt = 0; nt < 8; nt++)
#pragma unroll
            for (int r = 0; r < 4; r++) c[mt][nt][r] = 0.f;

#define LOAD_STAGE(s, kb) do { \
    uint32_t da = sb + (s) * STG + r8 * ROW_B + c8 * 16; \
    const __half* ga = Ag + (size_t)(kb) * BK + (size_t)r8 * K + c8 * 8; \
    _Pragma("unroll") \
    for (int p = 0; p < 8; p++) cpa16(da + p * 16 * ROW_B, ga + (size_t)p * 16 * K); \
    uint32_t db = sb + (s) * STG + STG_A + r8 * ROW_B + c8 * 16; \
    const __half* gb = Bg + (size_t)(kb) * BK + (size_t)r8 * K + c8 * 8; \
    _Pragma("unroll") \
    for (int p = 0; p < 8; p++) cpa16(db + p * 16 * ROW_B, gb + (size_t)p * 16 * K); \
    asm volatile("cp.async.commit_group;" ::: "memory"); \
} while (0)

    LOAD_STAGE(0, 0);
    LOAD_STAGE(1, 1);

    const uint32_t aoff = (wm * 64 + (lane & 7) + ((lane >> 3) & 1) * 8) * ROW_B + (lane >> 4) * 16;
    const uint32_t boff = STG_A + (wn * 64 + (lane & 7) + ((lane >> 4) & 1) * 8) * ROW_B
                          + ((lane >> 3) & 1) * 16;
    const int KB = K / BK;   // 8

    for (int kb = 0; kb < KB; kb++) {
        if (kb + 2 < KB) asm volatile("cp.async.wait_group 1;" ::: "memory");
        else             asm volatile("cp.async.wait_group 0;" ::: "memory");
        __syncthreads();
        if (kb + 2 < KB) { int s = (kb + 2) % NSTG; LOAD_STAGE(s, kb + 2); }

        uint32_t ab = sb + (kb % NSTG) * STG + aoff;
        uint32_t bb = sb + (kb % NSTG) * STG + boff;
#pragma unroll
        for (int ks = 0; ks < 4; ks++) {
            uint32_t a[4][4], b[4][4];
#pragma unroll
            for (int mt = 0; mt < 4; mt++) ldsm4(a[mt], ab + mt * 16 * ROW_B + ks * 32);
#pragma unroll
            for (int jt = 0; jt < 4; jt++) ldsm4(b[jt], bb + jt * 16 * ROW_B + ks * 32);
#pragma unroll
            for (int mt = 0; mt < 4; mt++)
#pragma unroll
                for (int nt = 0; nt < 8; nt++)
                    mma_f16(c[mt][nt], a[mt], b[nt >> 1][(nt & 1) * 2], b[nt >> 1][(nt & 1) * 2 + 1]);
        }
    }

    // epilogue: direct stores with bias
#pragma unroll
    for (int nt = 0; nt < 8; nt++) {
        int col = n0 + wn * 64 + nt * 8 + (lane & 3) * 2;
        float2 bv = *(const float2*)(bias + col);
        if (HOUT) {
            __half* Cp = (__half*)Cout;
#pragma unroll
            for (int mt = 0; mt < 4; mt++) {
                int r = m0 + wm * 64 + mt * 16 + (lane >> 2);
                *(half2*)(Cp + (size_t)r * N + col) =
                    __floats2half2_rn(c[mt][nt][0] + bv.x, c[mt][nt][1] + bv.y);
                *(half2*)(Cp + (size_t)(r + 8) * N + col) =
                    __floats2half2_rn(c[mt][nt][2] + bv.x, c[mt][nt][3] + bv.y);
            }
        } else {
            float* Cp = (float*)Cout;
#pragma unroll
            for (int mt = 0; mt < 4; mt++) {
                int r = m0 + wm * 64 + mt * 16 + (lane >> 2);
                *(float2*)(Cp + (size_t)r * N + col) =
                    make_float2(c[mt][nt][0] + bv.x, c[mt][nt][1] + bv.y);
                *(float2*)(Cp + (size_t)(r + 8) * N + col) =
                    make_float2(c[mt][nt][2] + bv.x, c[mt][nt][3] + bv.y);
            }
        }
    }
#undef LOAD_STAGE
}

// ---------------- fused window attention (fp16 mma) ----------------
// One CTA per (window b, head h). 128 threads (4 warps x 16 query rows).
__global__ __launch_bounds__(128)
void attn_kernel(const float* __restrict__ mask) {
    __shared__ __align__(16) __half q_s[64][40];
    __shared__ __align__(16) __half k_s[64][40];
    __shared__ __align__(16) __half v_s[64][40];
    __shared__ __align__(16) float  s_f[64][68];
    __shared__ __align__(16) __half p_h[64][72];
    __shared__ float  rsum[64];

    const int tid = threadIdx.x, lane = tid & 31, warp = tid >> 5;
    const int h = blockIdx.x, b = blockIdx.y, w = b & (NWIN - 1);

    const __half* base = g_qkv_h + (size_t)b * NTOK * 3 * CDIM + h * 32;

    // load q,k,v (64 rows x 32 halves each); 2 threads/row, 16 halves (2x uint4) each
    {
        int rr = tid >> 1, hc = (tid & 1) * 16;
        const __half* gp = base + (size_t)rr * (3 * CDIM);
        *(uint4*)&q_s[rr][hc]     = *(const uint4*)(gp + hc);
        *(uint4*)&q_s[rr][hc + 8] = *(const uint4*)(gp + hc + 8);
        *(uint4*)&k_s[rr][hc]     = *(const uint4*)(gp + CDIM + hc);
        *(uint4*)&k_s[rr][hc + 8] = *(const uint4*)(gp + CDIM + hc + 8);
        *(uint4*)&v_s[rr][hc]     = *(const uint4*)(gp + 2 * CDIM + hc);
        *(uint4*)&v_s[rr][hc + 8] = *(const uint4*)(gp + 2 * CDIM + hc + 8);
    }
    __syncthreads();

    // ---- S = Q K^T ----
    float sc[8][4];
#pragma unroll
    for (int nt = 0; nt < 8; nt++)
#pragma unroll
        for (int r = 0; r < 4; r++) sc[nt][r] = 0.f;

    uint32_t qa = s2u(q_s) + (warp * 16 + (lane & 15)) * 80 + (lane >> 4) * 16;
    uint32_t ka = s2u(k_s) + ((lane & 7) + ((lane >> 4) & 1) * 8) * 80 + ((lane >> 3) & 1) * 16;
#pragma unroll
    for (int ks = 0; ks < 2; ks++) {
        uint32_t aq[4];
        ldsm4(aq, qa + ks * 32);
        uint32_t bk[4][4];
#pragma unroll
        for (int jt = 0; jt < 4; jt++) ldsm4(bk[jt], ka + jt * 16 * 80 + ks * 32);
#pragma unroll
        for (int nt = 0; nt < 8; nt++)
            mma_f16(sc[nt], aq, bk[nt >> 1][(nt & 1) * 2], bk[nt >> 1][(nt & 1) * 2 + 1]);
    }

    // ---- scale + rpb + mask -> s_f ----
    const float scale = 0.17677669529663687f;   // 32^-0.5
    const float* rpbh = g_rpb + h * 4096;
    const float* mkw  = mask + (size_t)w * 4096;
    {
        int r = warp * 16 + (lane >> 2);
#pragma unroll
        for (int nt = 0; nt < 8; nt++) {
            int col = nt * 8 + (lane & 3) * 2;
            float2 rb0 = *(const float2*)(rpbh + r * 64 + col);
            float2 mk0 = *(const float2*)(mkw + r * 64 + col);
            s_f[r][col]     = sc[nt][0] * scale + rb0.x + mk0.x;
            s_f[r][col + 1] = sc[nt][1] * scale + rb0.y + mk0.y;
            float2 rb1 = *(const float2*)(rpbh + (r + 8) * 64 + col);
            float2 mk1 = *(const float2*)(mkw + (r + 8) * 64 + col);
            s_f[r + 8][col]     = sc[nt][2] * scale + rb1.x + mk1.x;
            s_f[r + 8][col + 1] = sc[nt][3] * scale + rb1.y + mk1.y;
        }
    }
    __syncthreads();

    // ---- softmax (unnormalized exp, fp32 sum, half P) ----
    {
        int row = tid >> 1;
        int c0  = (tid & 1) * 32;
        float mx = -1e30f;
#pragma unroll
        for (int j = 0; j < 32; j++) mx = fmaxf(mx, s_f[row][c0 + j]);
        mx = fmaxf(mx, __shfl_xor_sync(0xffffffff, mx, 1));
        float sum = 0.f;
#pragma unroll
        for (int j = 0; j < 32; j += 2) {
            float e0 = __expf(s_f[row][c0 + j]     - mx);
            float e1 = __expf(s_f[row][c0 + j + 1] - mx);
            sum += e0 + e1;
            *(half2*)&p_h[row][c0 + j] = __floats2half2_rn(e0, e1);
        }
        sum += __shfl_xor_sync(0xffffffff, sum, 1);
        if ((tid & 1) == 0) rsum[row] = sum;
    }
    __syncthreads();

    // ---- O = P V ----
    float oc[4][4];
#pragma unroll
    for (int nt = 0; nt < 4; nt++)
#pragma unroll
        for (int r = 0; r < 4; r++) oc[nt][r] = 0.f;

    uint32_t pa = s2u(p_h) + (warp * 16 + (lane & 15)) * 144 + (lane >> 4) * 16;
    uint32_t va = s2u(v_s) + ((lane & 7) + ((lane >> 3) & 1) * 8) * 80 + ((lane >> 4) & 1) * 16;
#pragma unroll
    for (int ks = 0; ks < 4; ks++) {
        uint32_t ap[4];
        ldsm4(ap, pa + ks * 32);
        uint32_t bv[2][4];
        ldsm4t(bv[0], va + ks * 16 * 80);
        ldsm4t(bv[1], va + ks * 16 * 80 + 32);
#pragma unroll
        for (int nt = 0; nt < 4; nt++)
            mma_f16(oc[nt], ap, bv[nt >> 1][(nt & 1) * 2], bv[nt >> 1][(nt & 1) * 2 + 1]);
    }

    // ---- normalize + store half ----
    __half* op = g_att_h + (size_t)b * NTOK * CDIM + h * 32;
    int r = warp * 16 + (lane >> 2);
    float inv0 = 1.f / rsum[r];
    float inv1 = 1.f / rsum[r + 8];
#pragma unroll
    for (int nt = 0; nt < 4; nt++) {
        int d = nt * 8 + (lane & 3) * 2;
        *(half2*)(op + (size_t)r * CDIM + d) =
            __floats2half2_rn(oc[nt][0] * inv0, oc[nt][1] * inv0);
        *(half2*)(op + (size_t)(r + 8) * CDIM + d) =
            __floats2half2_rn(oc[nt][2] * inv1, oc[nt][3] * inv1);
    }
}

// ---------------- launcher ----------------
extern "C" void kernel_launch(void* const* d_in, const int* in_sizes, int n_in,
                              void* d_out, int out_size) {
    const float* x         = (const float*)d_in[0];
    const float* mask      = (const float*)d_in[1];
    const float* qkv_w     = (const float*)d_in[2];
    const float* q_bias    = (const float*)d_in[3];
    const float* v_bias    = (const float*)d_in[4];
    const float* rpb_table = (const float*)d_in[5];
    const float* proj_w    = (const float*)d_in[6];
    const float* proj_b    = (const float*)d_in[7];
    const int*   rel_index = (const int*)d_in[8];
    float* out = (float*)d_out;

    void *p_xh, *p_qkvh, *p_atth, *p_wqkv, *p_wproj, *p_qkvb;
    cudaGetSymbolAddress(&p_xh,    g_x_h);
    cudaGetSymbolAddress(&p_qkvh,  g_qkv_h);
    cudaGetSymbolAddress(&p_atth,  g_att_h);
    cudaGetSymbolAddress(&p_wqkv,  g_wqkv_h);
    cudaGetSymbolAddress(&p_wproj, g_wproj_h);
    cudaGetSymbolAddress(&p_qkvb,  g_qkvb);

    cudaFuncSetAttribute(gemm_h<true>,  cudaFuncAttributeMaxDynamicSharedMemorySize, GEMM_SMEM);
    cudaFuncSetAttribute(gemm_h<false>, cudaFuncAttributeMaxDynamicSharedMemorySize, GEMM_SMEM);

    // 1) convert inputs to half
    cvt_kernel<<<(MROWS * CDIM / 4 + 255) / 256, 256>>>(x, (__half*)p_xh, MROWS * CDIM / 4);
    cvt_kernel<<<(3 * CDIM * CDIM / 4 + 255) / 256, 256>>>(qkv_w, (__half*)p_wqkv, 3 * CDIM * CDIM / 4);
    cvt_kernel<<<(CDIM * CDIM / 4 + 255) / 256, 256>>>(proj_w, (__half*)p_wproj, CDIM * CDIM / 4);

    // 2) rpb gather + fused qkv bias
    prep_kernel<<<256, 256>>>(q_bias, v_bias, rpb_table, rel_index);

    // 3) QKV GEMM: [131072,512] x [1536,512]^T -> g_qkv_h (half out)
    gemm_h<true><<<dim3(1536 / 128, MROWS / 128), 128, GEMM_SMEM>>>(
        (const __half*)p_xh, (const __half*)p_wqkv, (const float*)p_qkvb,
        p_qkvh, 3 * CDIM, CDIM);

    // 4) fused window attention -> g_att_h
    attn_kernel<<<dim3(HEADS, BWIN), 128>>>(mask);

    // 5) proj GEMM: [131072,512] x [512,512]^T -> out (fp32)
    gemm_h<false><<<dim3(CDIM / 128, MROWS / 128), 128, GEMM_SMEM>>>(
        (const __half*)p_atth, (const __half*)p_wproj, proj_b,
        out, CDIM, CDIM);
}

// round 5
// speedup vs baseline: 1.8780x; 1.1157x over previous
#include <cuda_runtime.h>
#include <cuda_fp16.h>
#include <cstdint>

#define HEADS 16
#define CDIM  512
#define NTOK  64
#define BWIN  2048
#define NWIN  256
#define MROWS (BWIN * NTOK)        // 131072

// ---------------- static scratch ----------------
__device__ __half g_x_h[(size_t)MROWS * CDIM];          // x in half
__device__ __half g_qkv_h[(size_t)MROWS * 3 * CDIM];    // qkv in half
__device__ __half g_att_h[(size_t)MROWS * CDIM];        // attn out in half
__device__ __half g_wqkv_h[3 * CDIM * CDIM];
__device__ __half g_wproj_h[CDIM * CDIM];
__device__ float  g_rpb[HEADS * NTOK * NTOK];
__device__ float  g_qkvb[3 * CDIM];

// ---------------- helpers ----------------
__device__ __forceinline__ uint32_t s2u(const void* p) {
    uint32_t a;
    asm("{ .reg .u64 t; cvta.to.shared.u64 t, %1; cvt.u32.u64 %0, t; }" : "=r"(a) : "l"(p));
    return a;
}
__device__ __forceinline__ void cpa16(uint32_t dst, const void* src) {
    asm volatile("cp.async.cg.shared.global [%0], [%1], 16;" :: "r"(dst), "l"(src) : "memory");
}
__device__ __forceinline__ void ldsm4(uint32_t r[4], uint32_t a) {
    asm volatile("ldmatrix.sync.aligned.m8n8.x4.shared.b16 {%0,%1,%2,%3}, [%4];"
                 : "=r"(r[0]), "=r"(r[1]), "=r"(r[2]), "=r"(r[3]) : "r"(a));
}
__device__ __forceinline__ void ldsm4t(uint32_t r[4], uint32_t a) {
    asm volatile("ldmatrix.sync.aligned.m8n8.x4.trans.shared.b16 {%0,%1,%2,%3}, [%4];"
                 : "=r"(r[0]), "=r"(r[1]), "=r"(r[2]), "=r"(r[3]) : "r"(a));
}
__device__ __forceinline__ void mma_f16(float c[4], const uint32_t a[4],
                                        uint32_t b0, uint32_t b1) {
    asm volatile(
        "mma.sync.aligned.m16n8k16.row.col.f32.f16.f16.f32 "
        "{%0,%1,%2,%3}, {%4,%5,%6,%7}, {%8,%9}, {%0,%1,%2,%3};"
        : "+f"(c[0]), "+f"(c[1]), "+f"(c[2]), "+f"(c[3])
        : "r"(a[0]), "r"(a[1]), "r"(a[2]), "r"(a[3]), "r"(b0), "r"(b1));
}
__device__ __forceinline__ uint32_t pack_h2(float a, float b) {
    half2 h = __floats2half2_rn(a, b);
    return *reinterpret_cast<uint32_t*>(&h);
}

// ---------------- fp32 -> fp16 conversion ----------------
__global__ void cvt_kernel(const float* __restrict__ src, __half* __restrict__ dst, int n4) {
    int i = blockIdx.x * 256 + threadIdx.x;
    if (i < n4) {
        float4 v = ((const float4*)src)[i];
        ((half2*)dst)[2 * i]     = __floats2half2_rn(v.x, v.y);
        ((half2*)dst)[2 * i + 1] = __floats2half2_rn(v.z, v.w);
    }
}

// ---------------- prep: rpb gather + fused qkv bias ----------------
__global__ void prep_kernel(const float* __restrict__ q_bias,
                            const float* __restrict__ v_bias,
                            const float* __restrict__ rpb_table,
                            const int*   __restrict__ rel_index) {
    int idx = blockIdx.x * 256 + threadIdx.x;
    if (idx < 3 * CDIM) {
        float v = 0.f;
        if (idx < CDIM)           v = q_bias[idx];
        else if (idx >= 2 * CDIM) v = v_bias[idx - 2 * CDIM];
        g_qkvb[idx] = v;
    }
    if (idx < HEADS * NTOK * NTOK) {
        int h  = idx >> 12;
        int nm = idx & 4095;
        g_rpb[idx] = rpb_table[rel_index[nm] * HEADS + h];
    }
}

// ---------------- fp16 GEMM: C[M,N] = A[M,K] * B[N,K]^T + bias[N] ----------------
// CTA 128x128, BK=64, 4 warps (2x2) with 64x64 warp tiles, 3-stage cp.async.
#define BK      64
#define ROW_B   144                 // bytes per smem row (64 halves + 8 pad)
#define STG_A   (128 * ROW_B)       // 18432
#define STG     (2 * STG_A)         // 36864
#define NSTG    3
#define GEMM_SMEM (NSTG * STG)      // 110592

template<bool HOUT>
__global__ __launch_bounds__(128, 2)
void gemm_h(const __half* __restrict__ A, const __half* __restrict__ B,
            const float* __restrict__ bias, void* __restrict__ Cout,
            int N, int K) {
    extern __shared__ __align__(16) char smem[];
    const uint32_t sb = s2u(smem);
    const int tid = threadIdx.x, lane = tid & 31, warp = tid >> 5;
    const int wm = warp >> 1, wn = warp & 1;
    const int m0 = blockIdx.y * 128, n0 = blockIdx.x * 128;

    const __half* Ag = A + (size_t)m0 * K;
    const __half* Bg = B + (size_t)n0 * K;
    const int r8 = tid >> 3, c8 = tid & 7;

    float c[4][8][4];
#pragma unroll
    for (int mt = 0; mt < 4; mt++)
#pragma unroll
        for (int nt = 0; nt < 8; nt++)
#pragma unroll
            for (int r = 0; r < 4; r++) c[mt][nt][r] = 0.f;

#define LOAD_STAGE(s, kb) do { \
    uint32_t da = sb + (s) * STG + r8 * ROW_B + c8 * 16; \
    const __half* ga = Ag + (size_t)(kb) * BK + (size_t)r8 * K + c8 * 8; \
    _Pragma("unroll") \
    for (int p = 0; p < 8; p++) cpa16(da + p * 16 * ROW_B, ga + (size_t)p * 16 * K); \
    uint32_t db = sb + (s) * STG + STG_A + r8 * ROW_B + c8 * 16; \
    const __half* gb = Bg + (size_t)(kb) * BK + (size_t)r8 * K + c8 * 8; \
    _Pragma("unroll") \
    for (int p = 0; p < 8; p++) cpa16(db + p * 16 * ROW_B, gb + (size_t)p * 16 * K); \
    asm volatile("cp.async.commit_group;" ::: "memory"); \
} while (0)

    LOAD_STAGE(0, 0);
    LOAD_STAGE(1, 1);

    const uint32_t aoff = (wm * 64 + (lane & 7) + ((lane >> 3) & 1) * 8) * ROW_B + (lane >> 4) * 16;
    const uint32_t boff = STG_A + (wn * 64 + (lane & 7) + ((lane >> 4) & 1) * 8) * ROW_B
                          + ((lane >> 3) & 1) * 16;
    const int KB = K / BK;   // 8

    for (int kb = 0; kb < KB; kb++) {
        if (kb + 2 < KB) asm volatile("cp.async.wait_group 1;" ::: "memory");
        else             asm volatile("cp.async.wait_group 0;" ::: "memory");
        __syncthreads();
        if (kb + 2 < KB) { int s = (kb + 2) % NSTG; LOAD_STAGE(s, kb + 2); }

        uint32_t ab = sb + (kb % NSTG) * STG + aoff;
        uint32_t bb = sb + (kb % NSTG) * STG + boff;
#pragma unroll
        for (int ks = 0; ks < 4; ks++) {
            uint32_t a[4][4], b[4][4];
#pragma unroll
            for (int mt = 0; mt < 4; mt++) ldsm4(a[mt], ab + mt * 16 * ROW_B + ks * 32);
#pragma unroll
            for (int jt = 0; jt < 4; jt++) ldsm4(b[jt], bb + jt * 16 * ROW_B + ks * 32);
#pragma unroll
            for (int mt = 0; mt < 4; mt++)
#pragma unroll
                for (int nt = 0; nt < 8; nt++)
                    mma_f16(c[mt][nt], a[mt], b[nt >> 1][(nt & 1) * 2], b[nt >> 1][(nt & 1) * 2 + 1]);
        }
    }

    // epilogue: direct stores with bias
#pragma unroll
    for (int nt = 0; nt < 8; nt++) {
        int col = n0 + wn * 64 + nt * 8 + (lane & 3) * 2;
        float2 bv = *(const float2*)(bias + col);
        if (HOUT) {
            __half* Cp = (__half*)Cout;
#pragma unroll
            for (int mt = 0; mt < 4; mt++) {
                int r = m0 + wm * 64 + mt * 16 + (lane >> 2);
                *(half2*)(Cp + (size_t)r * N + col) =
                    __floats2half2_rn(c[mt][nt][0] + bv.x, c[mt][nt][1] + bv.y);
                *(half2*)(Cp + (size_t)(r + 8) * N + col) =
                    __floats2half2_rn(c[mt][nt][2] + bv.x, c[mt][nt][3] + bv.y);
            }
        } else {
            float* Cp = (float*)Cout;
#pragma unroll
            for (int mt = 0; mt < 4; mt++) {
                int r = m0 + wm * 64 + mt * 16 + (lane >> 2);
                *(float2*)(Cp + (size_t)r * N + col) =
                    make_float2(c[mt][nt][0] + bv.x, c[mt][nt][1] + bv.y);
                *(float2*)(Cp + (size_t)(r + 8) * N + col) =
                    make_float2(c[mt][nt][2] + bv.x, c[mt][nt][3] + bv.y);
            }
        }
    }
#undef LOAD_STAGE
}

// ---------------- fused window attention (register-resident flash style) ----
// One CTA per (window b, head h). 128 threads; warp w owns query rows 16w..16w+15.
// S fragments -> softmax in registers (quad shfl) -> P fragments reused as
// mma A operand directly. Only q/k/v tiles in smem; ONE __syncthreads().
__global__ __launch_bounds__(128)
void attn_kernel(const float* __restrict__ mask) {
    __shared__ __align__(16) __half q_s[64][40];
    __shared__ __align__(16) __half k_s[64][40];
    __shared__ __align__(16) __half v_s[64][40];

    const int tid = threadIdx.x, lane = tid & 31, warp = tid >> 5;
    const int h = blockIdx.x, b = blockIdx.y, w = b & (NWIN - 1);

    const __half* base = g_qkv_h + (size_t)b * NTOK * 3 * CDIM + h * 32;

    // load q,k,v (64 rows x 32 halves each); 2 threads/row, 16 halves each
    {
        int rr = tid >> 1, hc = (tid & 1) * 16;
        const __half* gp = base + (size_t)rr * (3 * CDIM);
        *(uint4*)&q_s[rr][hc]     = *(const uint4*)(gp + hc);
        *(uint4*)&q_s[rr][hc + 8] = *(const uint4*)(gp + hc + 8);
        *(uint4*)&k_s[rr][hc]     = *(const uint4*)(gp + CDIM + hc);
        *(uint4*)&k_s[rr][hc + 8] = *(const uint4*)(gp + CDIM + hc + 8);
        *(uint4*)&v_s[rr][hc]     = *(const uint4*)(gp + 2 * CDIM + hc);
        *(uint4*)&v_s[rr][hc + 8] = *(const uint4*)(gp + 2 * CDIM + hc + 8);
    }
    __syncthreads();

    // ---- S = Q K^T ----
    float sc[8][4];
#pragma unroll
    for (int nt = 0; nt < 8; nt++)
#pragma unroll
        for (int r = 0; r < 4; r++) sc[nt][r] = 0.f;

    uint32_t qa = s2u(q_s) + (warp * 16 + (lane & 15)) * 80 + (lane >> 4) * 16;
    uint32_t ka = s2u(k_s) + ((lane & 7) + ((lane >> 4) & 1) * 8) * 80 + ((lane >> 3) & 1) * 16;
#pragma unroll
    for (int ks = 0; ks < 2; ks++) {
        uint32_t aq[4];
        ldsm4(aq, qa + ks * 32);
        uint32_t bk[4][4];
#pragma unroll
        for (int jt = 0; jt < 4; jt++) ldsm4(bk[jt], ka + jt * 16 * 80 + ks * 32);
#pragma unroll
        for (int nt = 0; nt < 8; nt++)
            mma_f16(sc[nt], aq, bk[nt >> 1][(nt & 1) * 2], bk[nt >> 1][(nt & 1) * 2 + 1]);
    }

    // ---- scale + rpb + mask (fragment epilogue, fp32) ----
    const float scale = 0.17677669529663687f;   // 32^-0.5
    const int r = warp * 16 + (lane >> 2);
    {
        const float* rpbh = g_rpb + h * 4096;
        const float* mkw  = mask + (size_t)w * 4096;
#pragma unroll
        for (int nt = 0; nt < 8; nt++) {
            int col = nt * 8 + (lane & 3) * 2;
            float2 rb0 = *(const float2*)(rpbh + r * 64 + col);
            float2 mk0 = *(const float2*)(mkw + r * 64 + col);
            sc[nt][0] = fmaf(sc[nt][0], scale, rb0.x + mk0.x);
            sc[nt][1] = fmaf(sc[nt][1], scale, rb0.y + mk0.y);
            float2 rb1 = *(const float2*)(rpbh + (r + 8) * 64 + col);
            float2 mk1 = *(const float2*)(mkw + (r + 8) * 64 + col);
            sc[nt][2] = fmaf(sc[nt][2], scale, rb1.x + mk1.x);
            sc[nt][3] = fmaf(sc[nt][3], scale, rb1.y + mk1.y);
        }
    }

    // ---- softmax fully in registers (quad reduction over lanes^1, ^2) ----
    float mx0 = -1e30f, mx1 = -1e30f;
#pragma unroll
    for (int nt = 0; nt < 8; nt++) {
        mx0 = fmaxf(mx0, fmaxf(sc[nt][0], sc[nt][1]));
        mx1 = fmaxf(mx1, fmaxf(sc[nt][2], sc[nt][3]));
    }
    mx0 = fmaxf(mx0, __shfl_xor_sync(0xffffffff, mx0, 1));
    mx0 = fmaxf(mx0, __shfl_xor_sync(0xffffffff, mx0, 2));
    mx1 = fmaxf(mx1, __shfl_xor_sync(0xffffffff, mx1, 1));
    mx1 = fmaxf(mx1, __shfl_xor_sync(0xffffffff, mx1, 2));

    float s0 = 0.f, s1 = 0.f;
#pragma unroll
    for (int nt = 0; nt < 8; nt++) {
        sc[nt][0] = __expf(sc[nt][0] - mx0);
        sc[nt][1] = __expf(sc[nt][1] - mx0);
        s0 += sc[nt][0] + sc[nt][1];
        sc[nt][2] = __expf(sc[nt][2] - mx1);
        sc[nt][3] = __expf(sc[nt][3] - mx1);
        s1 += sc[nt][2] + sc[nt][3];
    }
    s0 += __shfl_xor_sync(0xffffffff, s0, 1);
    s0 += __shfl_xor_sync(0xffffffff, s0, 2);
    s1 += __shfl_xor_sync(0xffffffff, s1, 1);
    s1 += __shfl_xor_sync(0xffffffff, s1, 2);
    const float inv0 = 1.f / s0, inv1 = 1.f / s1;

    // ---- O = P V : P fragments packed directly from S fragments ----
    float oc[4][4];
#pragma unroll
    for (int nt = 0; nt < 4; nt++)
#pragma unroll
        for (int rr = 0; rr < 4; rr++) oc[nt][rr] = 0.f;

    uint32_t va = s2u(v_s) + ((lane & 7) + ((lane >> 3) & 1) * 8) * 80 + ((lane >> 4) & 1) * 16;
#pragma unroll
    for (int ks = 0; ks < 4; ks++) {
        uint32_t ap[4];
        ap[0] = pack_h2(sc[2 * ks][0],     sc[2 * ks][1]);
        ap[1] = pack_h2(sc[2 * ks][2],     sc[2 * ks][3]);
        ap[2] = pack_h2(sc[2 * ks + 1][0], sc[2 * ks + 1][1]);
        ap[3] = pack_h2(sc[2 * ks + 1][2], sc[2 * ks + 1][3]);
        uint32_t bv[2][4];
        ldsm4t(bv[0], va + ks * 16 * 80);
        ldsm4t(bv[1], va + ks * 16 * 80 + 32);
#pragma unroll
        for (int nt = 0; nt < 4; nt++)
            mma_f16(oc[nt], ap, bv[nt >> 1][(nt & 1) * 2], bv[nt >> 1][(nt & 1) * 2 + 1]);
    }

    // ---- normalize + store half ----
    __half* op = g_att_h + (size_t)b * NTOK * CDIM + h * 32;
#pragma unroll
    for (int nt = 0; nt < 4; nt++) {
        int d = nt * 8 + (lane & 3) * 2;
        *(half2*)(op + (size_t)r * CDIM + d) =
            __floats2half2_rn(oc[nt][0] * inv0, oc[nt][1] * inv0);
        *(half2*)(op + (size_t)(r + 8) * CDIM + d) =
            __floats2half2_rn(oc[nt][2] * inv1, oc[nt][3] * inv1);
    }
}

// ---------------- launcher ----------------
extern "C" void kernel_launch(void* const* d_in, const int* in_sizes, int n_in,
                              void* d_out, int out_size) {
    const float* x         = (const float*)d_in[0];
    const float* mask      = (const float*)d_in[1];
    const float* qkv_w     = (const float*)d_in[2];
    const float* q_bias    = (const float*)d_in[3];
    const float* v_bias    = (const float*)d_in[4];
    const float* rpb_table = (const float*)d_in[5];
    const float* proj_w    = (const float*)d_in[6];
    const float* proj_b    = (const float*)d_in[7];
    const int*   rel_index = (const int*)d_in[8];
    float* out = (float*)d_out;

    void *p_xh, *p_qkvh, *p_atth, *p_wqkv, *p_wproj, *p_qkvb;
    cudaGetSymbolAddress(&p_xh,    g_x_h);
    cudaGetSymbolAddress(&p_qkvh,  g_qkv_h);
    cudaGetSymbolAddress(&p_atth,  g_att_h);
    cudaGetSymbolAddress(&p_wqkv,  g_wqkv_h);
    cudaGetSymbolAddress(&p_wproj, g_wproj_h);
    cudaGetSymbolAddress(&p_qkvb,  g_qkvb);

    cudaFuncSetAttribute(gemm_h<true>,  cudaFuncAttributeMaxDynamicSharedMemorySize, GEMM_SMEM);
    cudaFuncSetAttribute(gemm_h<false>, cudaFuncAttributeMaxDynamicSharedMemorySize, GEMM_SMEM);

    // 1) convert inputs to half
    cvt_kernel<<<(MROWS * CDIM / 4 + 255) / 256, 256>>>(x, (__half*)p_xh, MROWS * CDIM / 4);
    cvt_kernel<<<(3 * CDIM * CDIM / 4 + 255) / 256, 256>>>(qkv_w, (__half*)p_wqkv, 3 * CDIM * CDIM / 4);
    cvt_kernel<<<(CDIM * CDIM / 4 + 255) / 256, 256>>>(proj_w, (__half*)p_wproj, CDIM * CDIM / 4);

    // 2) rpb gather + fused qkv bias
    prep_kernel<<<256, 256>>>(q_bias, v_bias, rpb_table, rel_index);

    // 3) QKV GEMM: [131072,512] x [1536,512]^T -> g_qkv_h (half out)
    gemm_h<true><<<dim3(1536 / 128, MROWS / 128), 128, GEMM_SMEM>>>(
        (const __half*)p_xh, (const __half*)p_wqkv, (const float*)p_qkvb,
        p_qkvh, 3 * CDIM, CDIM);

    // 4) fused window attention -> g_att_h
    attn_kernel<<<dim3(HEADS, BWIN), 128>>>(mask);

    // 5) proj GEMM: [131072,512] x [512,512]^T -> out (fp32)
    gemm_h<false><<<dim3(CDIM / 128, MROWS / 128), 128, GEMM_SMEM>>>(
        (const __half*)p_atth, (const __half*)p_wproj, proj_b,
        out, CDIM, CDIM);
}

// round 6
// speedup vs baseline: 1.9290x; 1.0271x over previous
#include <cuda_runtime.h>
#include <cuda_fp16.h>
#include <cstdint>

#define HEADS 16
#define CDIM  512
#define NTOK  64
#define BWIN  2048
#define NWIN  256
#define MROWS (BWIN * NTOK)        // 131072

// ---------------- static scratch ----------------
__device__ __half g_x_h[(size_t)MROWS * CDIM];          // x in half
__device__ __half g_qkv_h[(size_t)MROWS * 3 * CDIM];    // qkv in half
__device__ __half g_att_h[(size_t)MROWS * CDIM];        // attn out in half
__device__ __half g_wqkv_h[3 * CDIM * CDIM];
__device__ __half g_wproj_h[CDIM * CDIM];
__device__ float  g_rpb[HEADS * NTOK * NTOK];
__device__ float  g_cmb[(size_t)NWIN * HEADS * NTOK * NTOK];  // rpb+mask combined (64MB)
__device__ float  g_qkvb[3 * CDIM];

// ---------------- helpers ----------------
__device__ __forceinline__ uint32_t s2u(const void* p) {
    uint32_t a;
    asm("{ .reg .u64 t; cvta.to.shared.u64 t, %1; cvt.u32.u64 %0, t; }" : "=r"(a) : "l"(p));
    return a;
}
__device__ __forceinline__ void cpa16(uint32_t dst, const void* src) {
    asm volatile("cp.async.cg.shared.global [%0], [%1], 16;" :: "r"(dst), "l"(src) : "memory");
}
__device__ __forceinline__ void ldsm4(uint32_t r[4], uint32_t a) {
    asm volatile("ldmatrix.sync.aligned.m8n8.x4.shared.b16 {%0,%1,%2,%3}, [%4];"
                 : "=r"(r[0]), "=r"(r[1]), "=r"(r[2]), "=r"(r[3]) : "r"(a));
}
__device__ __forceinline__ void ldsm4t(uint32_t r[4], uint32_t a) {
    asm volatile("ldmatrix.sync.aligned.m8n8.x4.trans.shared.b16 {%0,%1,%2,%3}, [%4];"
                 : "=r"(r[0]), "=r"(r[1]), "=r"(r[2]), "=r"(r[3]) : "r"(a));
}
__device__ __forceinline__ void mma_f16(float c[4], const uint32_t a[4],
                                        uint32_t b0, uint32_t b1) {
    asm volatile(
        "mma.sync.aligned.m16n8k16.row.col.f32.f16.f16.f32 "
        "{%0,%1,%2,%3}, {%4,%5,%6,%7}, {%8,%9}, {%0,%1,%2,%3};"
        : "+f"(c[0]), "+f"(c[1]), "+f"(c[2]), "+f"(c[3])
        : "r"(a[0]), "r"(a[1]), "r"(a[2]), "r"(a[3]), "r"(b0), "r"(b1));
}
__device__ __forceinline__ uint32_t pack_h2(float a, float b) {
    half2 h = __floats2half2_rn(a, b);
    return *reinterpret_cast<uint32_t*>(&h);
}

// ---------------- fp32 -> fp16 conversion ----------------
__global__ void cvt_kernel(const float* __restrict__ src, __half* __restrict__ dst, int n4) {
    int i = blockIdx.x * 256 + threadIdx.x;
    if (i < n4) {
        float4 v = ((const float4*)src)[i];
        ((half2*)dst)[2 * i]     = __floats2half2_rn(v.x, v.y);
        ((half2*)dst)[2 * i + 1] = __floats2half2_rn(v.z, v.w);
    }
}

// ---------------- prep: rpb gather + fused qkv bias ----------------
__global__ void prep_kernel(const float* __restrict__ q_bias,
                            const float* __restrict__ v_bias,
                            const float* __restrict__ rpb_table,
                            const int*   __restrict__ rel_index) {
    int idx = blockIdx.x * 256 + threadIdx.x;
    if (idx < 3 * CDIM) {
        float v = 0.f;
        if (idx < CDIM)           v = q_bias[idx];
        else if (idx >= 2 * CDIM) v = v_bias[idx - 2 * CDIM];
        g_qkvb[idx] = v;
    }
    if (idx < HEADS * NTOK * NTOK) {
        int h  = idx >> 12;
        int nm = idx & 4095;
        g_rpb[idx] = rpb_table[rel_index[nm] * HEADS + h];
    }
}

// ---------------- prep2: combined bias table cmb[w][h] = rpb[h] + mask[w] ----
__global__ void prep2_kernel(const float* __restrict__ mask) {
    int i = blockIdx.x * 256 + threadIdx.x;      // float4 index
    // total float4 = NWIN*HEADS*4096/4 = 4194304
    int nm4 = i & 1023;          // (64*64/4)
    int wh  = i >> 10;
    int h = wh & (HEADS - 1), w = wh >> 4;
    float4 rb = ((const float4*)g_rpb)[(h << 10) + nm4];
    float4 mk = ((const float4*)mask)[((size_t)w << 10) + nm4];
    float4 o;
    o.x = rb.x + mk.x; o.y = rb.y + mk.y; o.z = rb.z + mk.z; o.w = rb.w + mk.w;
    ((float4*)g_cmb)[i] = o;
}

// ---------------- fp16 GEMM: C[M,N] = A[M,K] * B[N,K]^T + bias[N] ----------------
// CTA 128x128, BK=64, 8 warps (4M x 2N) with 32x64 warp tiles, 3-stage cp.async.
#define BK      64
#define ROW_B   144                 // bytes per smem row (64 halves + 8 pad)
#define STG_A   (128 * ROW_B)       // 18432
#define STG     (2 * STG_A)         // 36864
#define NSTG    3
#define GEMM_SMEM (NSTG * STG)      // 110592

template<bool HOUT>
__global__ __launch_bounds__(256, 2)
void gemm_h(const __half* __restrict__ A, const __half* __restrict__ B,
            const float* __restrict__ bias, void* __restrict__ Cout,
            int N, int K) {
    extern __shared__ __align__(16) char smem[];
    const uint32_t sb = s2u(smem);
    const int tid = threadIdx.x, lane = tid & 31, warp = tid >> 5;
    const int wm = warp & 3, wn = warp >> 2;     // 4M x 2N warp grid
    const int m0 = blockIdx.y * 128, n0 = blockIdx.x * 128;

    const __half* Ag = A + (size_t)m0 * K;
    const __half* Bg = B + (size_t)n0 * K;

    float c[2][8][4];
#pragma unroll
    for (int mt = 0; mt < 2; mt++)
#pragma unroll
        for (int nt = 0; nt < 8; nt++)
#pragma unroll
            for (int r = 0; r < 4; r++) c[mt][nt][r] = 0.f;

#define LOAD_STAGE(s, kb) do { \
    _Pragma("unroll") \
    for (int i = 0; i < 4; i++) { \
        int f = tid + 256 * i;                /* 0..1023 chunk id */ \
        int row = f >> 3; int cc = f & 7; \
        cpa16(sb + (s) * STG + row * ROW_B + cc * 16, \
              Ag + (size_t)(kb) * BK + (size_t)row * K + cc * 8); \
        cpa16(sb + (s) * STG + STG_A + row * ROW_B + cc * 16, \
              Bg + (size_t)(kb) * BK + (size_t)row * K + cc * 8); \
    } \
    asm volatile("cp.async.commit_group;" ::: "memory"); \
} while (0)

    LOAD_STAGE(0, 0);
    LOAD_STAGE(1, 1);

    const uint32_t aoff = (wm * 32 + (lane & 15)) * ROW_B + (lane >> 4) * 16;
    const uint32_t boff = STG_A + (wn * 64 + (lane & 7) + ((lane >> 4) & 1) * 8) * ROW_B
                          + ((lane >> 3) & 1) * 16;
    const int KB = K / BK;   // 8

    for (int kb = 0; kb < KB; kb++) {
        if (kb + 2 < KB) asm volatile("cp.async.wait_group 1;" ::: "memory");
        else             asm volatile("cp.async.wait_group 0;" ::: "memory");
        __syncthreads();
        if (kb + 2 < KB) { int s = (kb + 2) % NSTG; LOAD_STAGE(s, kb + 2); }

        uint32_t ab = sb + (kb % NSTG) * STG + aoff;
        uint32_t bb = sb + (kb % NSTG) * STG + boff;
#pragma unroll
        for (int ks = 0; ks < 4; ks++) {
            uint32_t a[2][4], b[4][4];
#pragma unroll
            for (int mt = 0; mt < 2; mt++) ldsm4(a[mt], ab + mt * 16 * ROW_B + ks * 32);
#pragma unroll
            for (int jt = 0; jt < 4; jt++) ldsm4(b[jt], bb + jt * 16 * ROW_B + ks * 32);
#pragma unroll
            for (int mt = 0; mt < 2; mt++)
#pragma unroll
                for (int nt = 0; nt < 8; nt++)
                    mma_f16(c[mt][nt], a[mt], b[nt >> 1][(nt & 1) * 2], b[nt >> 1][(nt & 1) * 2 + 1]);
        }
    }

    // epilogue: direct stores with bias
#pragma unroll
    for (int nt = 0; nt < 8; nt++) {
        int col = n0 + wn * 64 + nt * 8 + (lane & 3) * 2;
        float2 bv = *(const float2*)(bias + col);
        if (HOUT) {
            __half* Cp = (__half*)Cout;
#pragma unroll
            for (int mt = 0; mt < 2; mt++) {
                int r = m0 + wm * 32 + mt * 16 + (lane >> 2);
                *(half2*)(Cp + (size_t)r * N + col) =
                    __floats2half2_rn(c[mt][nt][0] + bv.x, c[mt][nt][1] + bv.y);
                *(half2*)(Cp + (size_t)(r + 8) * N + col) =
                    __floats2half2_rn(c[mt][nt][2] + bv.x, c[mt][nt][3] + bv.y);
            }
        } else {
            float* Cp = (float*)Cout;
#pragma unroll
            for (int mt = 0; mt < 2; mt++) {
                int r = m0 + wm * 32 + mt * 16 + (lane >> 2);
                *(float2*)(Cp + (size_t)r * N + col) =
                    make_float2(c[mt][nt][0] + bv.x, c[mt][nt][1] + bv.y);
                *(float2*)(Cp + (size_t)(r + 8) * N + col) =
                    make_float2(c[mt][nt][2] + bv.x, c[mt][nt][3] + bv.y);
            }
        }
    }
#undef LOAD_STAGE
}

// ---------------- fused window attention (register-resident flash style) ----
// One CTA per (window b, head h). 128 threads; warp w owns query rows 16w..16w+15.
__global__ __launch_bounds__(128)
void attn_kernel() {
    __shared__ __align__(16) __half q_s[64][40];
    __shared__ __align__(16) __half k_s[64][40];
    __shared__ __align__(16) __half v_s[64][40];

    const int tid = threadIdx.x, lane = tid & 31, warp = tid >> 5;
    const int h = blockIdx.x, b = blockIdx.y, w = b & (NWIN - 1);

    const __half* base = g_qkv_h + (size_t)b * NTOK * 3 * CDIM + h * 32;

    // load q,k,v (64 rows x 32 halves each); 2 threads/row, 16 halves each
    {
        int rr = tid >> 1, hc = (tid & 1) * 16;
        const __half* gp = base + (size_t)rr * (3 * CDIM);
        *(uint4*)&q_s[rr][hc]     = *(const uint4*)(gp + hc);
        *(uint4*)&q_s[rr][hc + 8] = *(const uint4*)(gp + hc + 8);
        *(uint4*)&k_s[rr][hc]     = *(const uint4*)(gp + CDIM + hc);
        *(uint4*)&k_s[rr][hc + 8] = *(const uint4*)(gp + CDIM + hc + 8);
        *(uint4*)&v_s[rr][hc]     = *(const uint4*)(gp + 2 * CDIM + hc);
        *(uint4*)&v_s[rr][hc + 8] = *(const uint4*)(gp + 2 * CDIM + hc + 8);
    }
    __syncthreads();

    // ---- S = Q K^T ----
    float sc[8][4];
#pragma unroll
    for (int nt = 0; nt < 8; nt++)
#pragma unroll
        for (int r = 0; r < 4; r++) sc[nt][r] = 0.f;

    uint32_t qa = s2u(q_s) + (warp * 16 + (lane & 15)) * 80 + (lane >> 4) * 16;
    uint32_t ka = s2u(k_s) + ((lane & 7) + ((lane >> 4) & 1) * 8) * 80 + ((lane >> 3) & 1) * 16;
#pragma unroll
    for (int ks = 0; ks < 2; ks++) {
        uint32_t aq[4];
        ldsm4(aq, qa + ks * 32);
        uint32_t bk[4][4];
#pragma unroll
        for (int jt = 0; jt < 4; jt++) ldsm4(bk[jt], ka + jt * 16 * 80 + ks * 32);
#pragma unroll
        for (int nt = 0; nt < 8; nt++)
            mma_f16(sc[nt], aq, bk[nt >> 1][(nt & 1) * 2], bk[nt >> 1][(nt & 1) * 2 + 1]);
    }

    // ---- scale + combined (rpb+mask) bias (fragment epilogue, fp32) ----
    const float scale = 0.17677669529663687f;   // 32^-0.5
    const int r = warp * 16 + (lane >> 2);
    {
        const float* cmb = g_cmb + ((size_t)(w * HEADS + h) << 12);
#pragma unroll
        for (int nt = 0; nt < 8; nt++) {
            int col = nt * 8 + (lane & 3) * 2;
            float2 c0 = *(const float2*)(cmb + r * 64 + col);
            sc[nt][0] = fmaf(sc[nt][0], scale, c0.x);
            sc[nt][1] = fmaf(sc[nt][1], scale, c0.y);
            float2 c1 = *(const float2*)(cmb + (r + 8) * 64 + col);
            sc[nt][2] = fmaf(sc[nt][2], scale, c1.x);
            sc[nt][3] = fmaf(sc[nt][3], scale, c1.y);
        }
    }

    // ---- softmax fully in registers (quad reduction over lanes^1, ^2) ----
    float mx0 = -1e30f, mx1 = -1e30f;
#pragma unroll
    for (int nt = 0; nt < 8; nt++) {
        mx0 = fmaxf(mx0, fmaxf(sc[nt][0], sc[nt][1]));
        mx1 = fmaxf(mx1, fmaxf(sc[nt][2], sc[nt][3]));
    }
    mx0 = fmaxf(mx0, __shfl_xor_sync(0xffffffff, mx0, 1));
    mx0 = fmaxf(mx0, __shfl_xor_sync(0xffffffff, mx0, 2));
    mx1 = fmaxf(mx1, __shfl_xor_sync(0xffffffff, mx1, 1));
    mx1 = fmaxf(mx1, __shfl_xor_sync(0xffffffff, mx1, 2));

    float s0 = 0.f, s1 = 0.f;
#pragma unroll
    for (int nt = 0; nt < 8; nt++) {
        sc[nt][0] = __expf(sc[nt][0] - mx0);
        sc[nt][1] = __expf(sc[nt][1] - mx0);
        s0 += sc[nt][0] + sc[nt][1];
        sc[nt][2] = __expf(sc[nt][2] - mx1);
        sc[nt][3] = __expf(sc[nt][3] - mx1);
        s1 += sc[nt][2] + sc[nt][3];
    }
    s0 += __shfl_xor_sync(0xffffffff, s0, 1);
    s0 += __shfl_xor_sync(0xffffffff, s0, 2);
    s1 += __shfl_xor_sync(0xffffffff, s1, 1);
    s1 += __shfl_xor_sync(0xffffffff, s1, 2);
    const float inv0 = 1.f / s0, inv1 = 1.f / s1;

    // ---- O = P V : P fragments packed directly from S fragments ----
    float oc[4][4];
#pragma unroll
    for (int nt = 0; nt < 4; nt++)
#pragma unroll
        for (int rr = 0; rr < 4; rr++) oc[nt][rr] = 0.f;

    uint32_t va = s2u(v_s) + ((lane & 7) + ((lane >> 3) & 1) * 8) * 80 + ((lane >> 4) & 1) * 16;
#pragma unroll
    for (int ks = 0; ks < 4; ks++) {
        uint32_t ap[4];
        ap[0] = pack_h2(sc[2 * ks][0],     sc[2 * ks][1]);
        ap[1] = pack_h2(sc[2 * ks][2],     sc[2 * ks][3]);
        ap[2] = pack_h2(sc[2 * ks + 1][0], sc[2 * ks + 1][1]);
        ap[3] = pack_h2(sc[2 * ks + 1][2], sc[2 * ks + 1][3]);
        uint32_t bv[2][4];
        ldsm4t(bv[0], va + ks * 16 * 80);
        ldsm4t(bv[1], va + ks * 16 * 80 + 32);
#pragma unroll
        for (int nt = 0; nt < 4; nt++)
            mma_f16(oc[nt], ap, bv[nt >> 1][(nt & 1) * 2], bv[nt >> 1][(nt & 1) * 2 + 1]);
    }

    // ---- normalize + store half ----
    __half* op = g_att_h + (size_t)b * NTOK * CDIM + h * 32;
#pragma unroll
    for (int nt = 0; nt < 4; nt++) {
        int d = nt * 8 + (lane & 3) * 2;
        *(half2*)(op + (size_t)r * CDIM + d) =
            __floats2half2_rn(oc[nt][0] * inv0, oc[nt][1] * inv0);
        *(half2*)(op + (size_t)(r + 8) * CDIM + d) =
            __floats2half2_rn(oc[nt][2] * inv1, oc[nt][3] * inv1);
    }
}

// ---------------- launcher ----------------
extern "C" void kernel_launch(void* const* d_in, const int* in_sizes, int n_in,
                              void* d_out, int out_size) {
    const float* x         = (const float*)d_in[0];
    const float* mask      = (const float*)d_in[1];
    const float* qkv_w     = (const float*)d_in[2];
    const float* q_bias    = (const float*)d_in[3];
    const float* v_bias    = (const float*)d_in[4];
    const float* rpb_table = (const float*)d_in[5];
    const float* proj_w    = (const float*)d_in[6];
    const float* proj_b    = (const float*)d_in[7];
    const int*   rel_index = (const int*)d_in[8];
    float* out = (float*)d_out;

    void *p_xh, *p_qkvh, *p_atth, *p_wqkv, *p_wproj, *p_qkvb;
    cudaGetSymbolAddress(&p_xh,    g_x_h);
    cudaGetSymbolAddress(&p_qkvh,  g_qkv_h);
    cudaGetSymbolAddress(&p_atth,  g_att_h);
    cudaGetSymbolAddress(&p_wqkv,  g_wqkv_h);
    cudaGetSymbolAddress(&p_wproj, g_wproj_h);
    cudaGetSymbolAddress(&p_qkvb,  g_qkvb);

    cudaFuncSetAttribute(gemm_h<true>,  cudaFuncAttributeMaxDynamicSharedMemorySize, GEMM_SMEM);
    cudaFuncSetAttribute(gemm_h<false>, cudaFuncAttributeMaxDynamicSharedMemorySize, GEMM_SMEM);

    // 1) convert inputs to half
    cvt_kernel<<<(MROWS * CDIM / 4 + 255) / 256, 256>>>(x, (__half*)p_xh, MROWS * CDIM / 4);
    cvt_kernel<<<(3 * CDIM * CDIM / 4 + 255) / 256, 256>>>(qkv_w, (__half*)p_wqkv, 3 * CDIM * CDIM / 4);
    cvt_kernel<<<(CDIM * CDIM / 4 + 255) / 256, 256>>>(proj_w, (__half*)p_wproj, CDIM * CDIM / 4);

    // 2) rpb gather + fused qkv bias, then combined bias table
    prep_kernel<<<256, 256>>>(q_bias, v_bias, rpb_table, rel_index);
    prep2_kernel<<<(NWIN * HEADS * 4096 / 4) / 256, 256>>>(mask);

    // 3) QKV GEMM: [131072,512] x [1536,512]^T -> g_qkv_h (half out)
    gemm_h<true><<<dim3(1536 / 128, MROWS / 128), 256, GEMM_SMEM>>>(
        (const __half*)p_xh, (const __half*)p_wqkv, (const float*)p_qkvb,
        p_qkvh, 3 * CDIM, CDIM);

    // 4) fused window attention -> g_att_h
    attn_kernel<<<dim3(HEADS, BWIN), 128>>>();

    // 5) proj GEMM: [131072,512] x [512,512]^T -> out (fp32)
    gemm_h<false><<<dim3(CDIM / 128, MROWS / 128), 256, GEMM_SMEM>>>(
        (const __half*)p_atth, (const __half*)p_wproj, proj_b,
        out, CDIM, CDIM);
}